// round 15
// baseline (speedup 1.0000x reference)
#include <cuda_runtime.h>
#include <math.h>

#define H1 256
#define W1 320
#define H2 128
#define W2 160
#define HOUT 512
#define WOUT 640
#define DEPTH 48
#define HW1 (H1*W1)
#define HW2 (H2*W2)
#define HWO (WOUT*HOUT)
#define NB2P2 (HW2/512)   /* 40  */
#define TILES_X 5         /* 320/64 */
#define TILE_N  320       /* tiles per slab: 64 * 5 */
#define DUPW 66
#define DUPH 6
#define DUPN (8*DUPH*DUPW)  /* 3168 u64 = 25344 B */

typedef unsigned long long u64;

// ---------------- scratch state ---------------------------------------------
__device__ float g_s1b[3][8  * HW1];
__device__ float g_s2b[2][16 * HW2];
__device__ float g_c2b[2][16 * HW2];
__device__ float g_upb[2][8  * HW1];
__device__ float g_u1 [8  * HW1];
__device__ float g_rh1[8  * HW1];
__device__ float g_u2 [16 * HW2];
__device__ float g_rh2[16 * HW2];
__device__ float g_c1a[DEPTH * 8 * HW1];

// ---------------- packed f32x2 helpers -------------------------------------
__device__ __forceinline__ u64 pack2(float lo, float hi) {
    u64 r; asm("mov.b64 %0, {%1, %2};" : "=l"(r) : "f"(lo), "f"(hi)); return r;
}
__device__ __forceinline__ void unpack2(u64 v, float& lo, float& hi) {
    asm("mov.b64 {%0, %1}, %2;" : "=f"(lo), "=f"(hi) : "l"(v));
}
__device__ __forceinline__ void ffma2(u64& d, u64 a, u64 b) {
    asm("fma.rn.f32x2 %0, %1, %2, %0;" : "+l"(d) : "l"(a), "l"(b));
}
__device__ __forceinline__ float sigf(float x) {
    return __fdividef(1.0f, 1.0f + __expf(-x));
}
__device__ __forceinline__ float tanh_fast(float x) {
    return __fdividef(2.0f, 1.0f + __expf(-2.0f * x)) - 1.0f;
}

// ---------------- weight loaders -------------------------------------------
template<int CIN_TOT, int CSEL, int COB>
__device__ __forceinline__ void load_w_slice(float* ws, const float* __restrict__ w,
                                             int co_base, int ci_off) {
    const int n = CSEL * 9 * COB;
    for (int i = threadIdx.x; i < n; i += blockDim.x) {
        int co   = i % COB;
        int rest = i / COB;
        int ci   = rest / 9;
        int k    = rest - ci * 9;
        ws[i] = w[(co_base + co) * (CIN_TOT * 9) + (ci_off + ci) * 9 + k];
    }
}
template<int CIN, int COB, int COUT_TOT>
__device__ __forceinline__ void load_w_deconv(float* ws, const float* __restrict__ w, int co_base) {
    const int n = CIN * 9 * COB;
    for (int i = threadIdx.x; i < n; i += blockDim.x) {
        int co   = i % COB;
        int rest = i / COB;
        int ci   = rest / 9;
        int k    = rest - ci * 9;
        ws[i] = w[(ci * COUT_TOT + co_base + co) * 9 + k];
    }
}

// ---------------- tiled smem input staging (level-1, 8 ci group) -------------
__device__ __forceinline__ void load_dup_tile(u64* dup, const float* __restrict__ src,
                                              int tileY, int tileX) {
    for (int idx = threadIdx.x; idx < DUPN; idx += 256) {
        int ci  = idx / (DUPH * DUPW);
        int rem = idx - ci * (DUPH * DUPW);
        int row = rem / DUPW;
        int col = rem - row * DUPW;
        int iy = tileY * 4 + row - 1;
        int ix = tileX + col - 1;
        float v = ((unsigned)iy < (unsigned)H1 && (unsigned)ix < (unsigned)W1)
                  ? __ldg(src + ci * HW1 + iy * W1 + ix) : 0.0f;
        dup[idx] = pack2(v, v);
    }
}
template<int COB>
__device__ __forceinline__ void accum_tile(u64 (&acc)[COB/2], const float* ws,
                                           const u64* dup, int ci_off, int r, int c) {
#pragma unroll
    for (int ci = 0; ci < 8; ci++) {
        const u64* dp = dup + ci * (DUPH * DUPW) + r * DUPW + c;
#pragma unroll
        for (int ky = 0; ky < 3; ky++) {
#pragma unroll
            for (int kx = 0; kx < 3; kx++) {
                u64 v = dp[ky * DUPW + kx];
                const u64* wp = (const u64*)(ws + ((ci_off + ci) * 9 + ky * 3 + kx) * COB);
#pragma unroll
                for (int cp = 0; cp < COB / 2; cp++)
                    ffma2(acc[cp], wp[cp], v);
            }
        }
    }
}

// ---------------- P2 accumulate cores (level-2 + bulk) ------------------------
template<int C, int COB, int CIU, bool GUARD>
__device__ __forceinline__ void accum_s1p2(u64 (&acc)[COB/2][2], const float* ws,
                                           const float* __restrict__ in, int cs,
                                           int y, int x0, int Hin, int Win) {
    const int bx = x0 - 1;
#pragma unroll CIU
    for (int ci = 0; ci < C; ci++) {
        const float* src = in + ci * cs;
        u64 vd[12];
#pragma unroll
        for (int ky = 0; ky < 3; ky++) {
            int iy = y + ky - 1;
            const float* rp = src + iy * Win;
#pragma unroll
            for (int j = 0; j < 4; j++) {
                float v;
                if (GUARD) {
                    int ix = bx + j;
                    v = ((unsigned)iy < (unsigned)Hin && (unsigned)ix < (unsigned)Win)
                        ? __ldg(rp + ix) : 0.0f;
                } else {
                    v = __ldg(rp + bx + j);
                }
                vd[ky * 4 + j] = pack2(v, v);
            }
        }
#pragma unroll
        for (int ky = 0; ky < 3; ky++) {
#pragma unroll
            for (int kx = 0; kx < 3; kx++) {
                const u64* wp = (const u64*)(ws + (ci * 9 + ky * 3 + kx) * COB);
#pragma unroll
                for (int cp = 0; cp < COB / 2; cp++) {
                    u64 w2 = wp[cp];
                    ffma2(acc[cp][0], w2, vd[ky * 4 + kx]);
                    ffma2(acc[cp][1], w2, vd[ky * 4 + kx + 1]);
                }
            }
        }
    }
}
__device__ __forceinline__ bool interior_s1p2(int y, int x0, int Hin, int Win) {
    return (y >= 1) & (y <= Hin - 2) & (x0 >= 1) & (x0 <= Win - 3);
}

template<int C, int COB, int CIU, bool GUARD>
__device__ __forceinline__ void accum_s2p2(u64 (&acc)[COB/2][2], const float* ws,
                                           const float* __restrict__ in, int cs,
                                           int y, int x0, int Hin, int Win) {
    const int bx = 2 * x0 - 1;
#pragma unroll CIU
    for (int ci = 0; ci < C; ci++) {
        const float* src = in + ci * cs;
#pragma unroll
        for (int ky = 0; ky < 3; ky++) {
            int iy = 2 * y + ky - 1;
            const float* rp = src + iy * Win;
            u64 vd[5];
#pragma unroll
            for (int j = 0; j < 5; j++) {
                float v;
                if (GUARD) {
                    int ix = bx + j;
                    v = ((unsigned)iy < (unsigned)Hin && (unsigned)ix < (unsigned)Win)
                        ? __ldg(rp + ix) : 0.0f;
                } else {
                    v = __ldg(rp + bx + j);
                }
                vd[j] = pack2(v, v);
            }
#pragma unroll
            for (int kx = 0; kx < 3; kx++) {
                const u64* wp = (const u64*)(ws + (ci * 9 + ky * 3 + kx) * COB);
#pragma unroll
                for (int cp = 0; cp < COB / 2; cp++) {
                    u64 w2 = wp[cp];
                    ffma2(acc[cp][0], w2, vd[kx]);
                    ffma2(acc[cp][1], w2, vd[kx + 2]);
                }
            }
        }
    }
}
__device__ __forceinline__ bool interior_s2p2(int y, int x0) {
    return (y >= 1) & (x0 >= 1);
}

template<int COB>
__device__ __forceinline__ void init_acc2(u64 (&acc)[COB/2][2], const float* __restrict__ b, int co_base) {
#pragma unroll
    for (int cp = 0; cp < COB/2; cp++) {
        u64 bb = pack2(__ldg(b + co_base + 2*cp), __ldg(b + co_base + 2*cp + 1));
        acc[cp][0] = bb; acc[cp][1] = bb;
    }
}

// ---------------- bulk precompute kernel -------------------------------------
__global__ void zero_k(float* a, int n) {
    int i = blockIdx.x * blockDim.x + threadIdx.x;
    if (i < n) a[i] = 0.0f;
}

__global__ void __launch_bounds__(256, 4) conv1_all_k(
        const float* __restrict__ vol, const float* __restrict__ w,
        const float* __restrict__ b, float* __restrict__ out) {
    constexpr int COB = 8;
    __shared__ __align__(16) float ws[32 * 9 * COB];
    load_w_slice<32, 32, COB>(ws, w, 0, 0);
    __syncthreads();
    int pg = (blockIdx.x * blockDim.x + threadIdx.x) * 2;
    int d  = pg / HW1;
    int px = pg - d * HW1;
    int y = px / W1, x0 = px - y * W1;
    u64 acc[COB/2][2];
    init_acc2<COB>(acc, b, 0);
    const float* in = vol + d * HW1;
    if (interior_s1p2(y, x0, H1, W1))
        accum_s1p2<32, COB, 4, false>(acc, ws, in, DEPTH * HW1, y, x0, H1, W1);
    else
        accum_s1p2<32, COB, 4, true >(acc, ws, in, DEPTH * HW1, y, x0, H1, W1);
    float* op = out + d * 8 * HW1 + px;
#pragma unroll
    for (int cp = 0; cp < COB/2; cp++) {
        float a00, a10, a01, a11;
        unpack2(acc[cp][0], a00, a10);
        unpack2(acc[cp][1], a01, a11);
        *(float2*)(op + (2*cp  ) * HW1) = make_float2(fmaxf(a00,0.f), fmaxf(a01,0.f));
        *(float2*)(op + (2*cp+1) * HW1) = make_float2(fmaxf(a10,0.f), fmaxf(a11,0.f));
    }
}

// ---------------- level-1 tiled parts ----------------------------------------
// gates1h: tiled smem, COB=8, 2 slabs x 320 tiles = 640 blocks.
__device__ __forceinline__ void gates1h_tile_part(
        const float* __restrict__ c1d, const float* __restrict__ s1r,
        const float* __restrict__ wg, const float* __restrict__ bg,
        float* __restrict__ u_out, float* __restrict__ rh_out,
        float* ws, u64* dup, int sub) {
    constexpr int COB = 8;
    int slab = sub / TILE_N;
    int co_base = slab * COB;
    load_w_slice<16, 16, COB>(ws, wg, co_base, 0);
    int tile = sub - slab * TILE_N;
    int tileY = tile / TILES_X;
    int tileX = (tile - tileY * TILES_X) * 64;
    int r = threadIdx.x >> 6;
    int c = threadIdx.x & 63;
    u64 acc[COB/2];
#pragma unroll
    for (int cp = 0; cp < COB/2; cp++)
        acc[cp] = pack2(__ldg(bg + co_base + 2*cp), __ldg(bg + co_base + 2*cp + 1));
    load_dup_tile(dup, c1d, tileY, tileX);
    __syncthreads();
    accum_tile<COB>(acc, ws, dup, 0, r, c);
    __syncthreads();
    load_dup_tile(dup, s1r, tileY, tileX);
    __syncthreads();
    accum_tile<COB>(acc, ws, dup, 8, r, c);
    int px = (tileY * 4 + r) * W1 + tileX + c;
    if (slab == 0) {
#pragma unroll
        for (int cp = 0; cp < COB/2; cp++) {
            float a0, a1; unpack2(acc[cp], a0, a1);
            rh_out[(2*cp  ) * HW1 + px] = sigf(a0) * __ldg(s1r + (2*cp  ) * HW1 + px);
            rh_out[(2*cp+1) * HW1 + px] = sigf(a1) * __ldg(s1r + (2*cp+1) * HW1 + px);
        }
    } else {
#pragma unroll
        for (int cp = 0; cp < COB/2; cp++) {
            float a0, a1; unpack2(acc[cp], a0, a1);
            u_out[(2*cp  ) * HW1 + px] = sigf(a0);
            u_out[(2*cp+1) * HW1 + px] = sigf(a1);
        }
    }
}

// cand1h: tiled smem, COB=8, 320 tiles = 320 blocks.
__device__ __forceinline__ void cand1h_tile_part(
        const float* __restrict__ c1d, const float* __restrict__ rh,
        const float* __restrict__ wc, const float* __restrict__ bc,
        const float* __restrict__ u, const float* __restrict__ s1old,
        float* __restrict__ s1new, float* ws, u64* dup, int sub) {
    constexpr int COB = 8;
    load_w_slice<16, 16, COB>(ws, wc, 0, 0);
    int tileY = sub / TILES_X;
    int tileX = (sub - tileY * TILES_X) * 64;
    int r = threadIdx.x >> 6;
    int c = threadIdx.x & 63;
    u64 acc[COB/2];
#pragma unroll
    for (int cp = 0; cp < COB/2; cp++)
        acc[cp] = pack2(__ldg(bc + 2*cp), __ldg(bc + 2*cp + 1));
    load_dup_tile(dup, c1d, tileY, tileX);
    __syncthreads();
    accum_tile<COB>(acc, ws, dup, 0, r, c);
    __syncthreads();
    load_dup_tile(dup, rh, tileY, tileX);
    __syncthreads();
    accum_tile<COB>(acc, ws, dup, 8, r, c);
    int px = (tileY * 4 + r) * W1 + tileX + c;
#pragma unroll
    for (int cp = 0; cp < COB/2; cp++) {
        float a0, a1; unpack2(acc[cp], a0, a1);
        int c0 = 2*cp, c1 = c0 + 1;
        float u0 = __ldg(u + c0 * HW1 + px), u1v = __ldg(u + c1 * HW1 + px);
        float h0 = __ldg(s1old + c0 * HW1 + px), h1 = __ldg(s1old + c1 * HW1 + px);
        s1new[c0 * HW1 + px] = u0 * h0 + (1.f - u0) * tanh_fast(a0);
        s1new[c1 * HW1 + px] = u1v * h1 + (1.f - u1v) * tanh_fast(a1);
    }
}

// ---------------- level-2 parts (R10 exact) ----------------------------------
__device__ __forceinline__ void conv2_part(
        const float* __restrict__ s1r, const float* __restrict__ w,
        const float* __restrict__ b, float* __restrict__ c2out,
        float* ws, int sub) {
    constexpr int COB = 4;
    int slab = sub / NB2P2;
    int co_base = slab * COB;
    load_w_slice<8, 8, COB>(ws, w, co_base, 0);
    __syncthreads();
    int px0 = ((sub - slab * NB2P2) * 256 + threadIdx.x) * 2;
    int y = px0 / W2, x0 = px0 - y * W2;
    u64 acc[COB/2][2];
    init_acc2<COB>(acc, b, co_base);
    if (interior_s2p2(y, x0))
        accum_s2p2<8, COB, 4, false>(acc, ws, s1r, HW1, y, x0, H1, W1);
    else
        accum_s2p2<8, COB, 4, true >(acc, ws, s1r, HW1, y, x0, H1, W1);
#pragma unroll
    for (int cp = 0; cp < COB/2; cp++) {
        float a00, a10, a01, a11;
        unpack2(acc[cp][0], a00, a10);
        unpack2(acc[cp][1], a01, a11);
        int c0 = co_base + 2*cp, c1 = c0 + 1;
        *(float2*)(c2out + c0 * HW2 + px0) = make_float2(fmaxf(a00,0.f), fmaxf(a01,0.f));
        *(float2*)(c2out + c1 * HW2 + px0) = make_float2(fmaxf(a10,0.f), fmaxf(a11,0.f));
    }
}

__device__ __forceinline__ void gates2_part(
        const float* __restrict__ c2r, const float* __restrict__ s2r,
        const float* __restrict__ wg, const float* __restrict__ bg,
        float* __restrict__ u_out, float* __restrict__ rh_out,
        float* ws, int sub) {
    constexpr int COB = 4;
    int slab = sub / NB2P2;
    int co_base = slab * COB;
    load_w_slice<32, 32, COB>(ws, wg, co_base, 0);
    __syncthreads();
    int px0 = ((sub - slab * NB2P2) * 256 + threadIdx.x) * 2;
    int y = px0 / W2, x0 = px0 - y * W2;
    u64 acc[COB/2][2];
    init_acc2<COB>(acc, bg, co_base);
    if (interior_s1p2(y, x0, H2, W2)) {
        accum_s1p2<16, COB, 4, false>(acc, ws,             c2r, HW2, y, x0, H2, W2);
        accum_s1p2<16, COB, 4, false>(acc, ws + 16*9*COB,  s2r, HW2, y, x0, H2, W2);
    } else {
        accum_s1p2<16, COB, 4, true >(acc, ws,             c2r, HW2, y, x0, H2, W2);
        accum_s1p2<16, COB, 4, true >(acc, ws + 16*9*COB,  s2r, HW2, y, x0, H2, W2);
    }
#pragma unroll
    for (int cp = 0; cp < COB/2; cp++) {
        float a00, a10, a01, a11;
        unpack2(acc[cp][0], a00, a10);
        unpack2(acc[cp][1], a01, a11);
        if (co_base < 16) {
            int c0 = co_base + 2*cp, c1 = c0 + 1;
            float2 h0 = *(const float2*)(s2r + c0 * HW2 + px0);
            float2 h1 = *(const float2*)(s2r + c1 * HW2 + px0);
            *(float2*)(rh_out + c0 * HW2 + px0) = make_float2(sigf(a00)*h0.x, sigf(a01)*h0.y);
            *(float2*)(rh_out + c1 * HW2 + px0) = make_float2(sigf(a10)*h1.x, sigf(a11)*h1.y);
        } else {
            int c0 = co_base - 16 + 2*cp, c1 = c0 + 1;
            *(float2*)(u_out + c0 * HW2 + px0) = make_float2(sigf(a00), sigf(a01));
            *(float2*)(u_out + c1 * HW2 + px0) = make_float2(sigf(a10), sigf(a11));
        }
    }
}

__device__ __forceinline__ void cand2_part(
        const float* __restrict__ c2r, const float* __restrict__ rh,
        const float* __restrict__ wc, const float* __restrict__ bc,
        const float* __restrict__ u, const float* __restrict__ s2old,
        float* __restrict__ s2new, float* ws, int sub) {
    constexpr int COB = 4;
    int slab = sub / NB2P2;
    int co_base = slab * COB;
    load_w_slice<32, 32, COB>(ws, wc, co_base, 0);
    __syncthreads();
    int px0 = ((sub - slab * NB2P2) * 256 + threadIdx.x) * 2;
    int y = px0 / W2, x0 = px0 - y * W2;
    u64 acc[COB/2][2];
    init_acc2<COB>(acc, bc, co_base);
    if (interior_s1p2(y, x0, H2, W2)) {
        accum_s1p2<16, COB, 4, false>(acc, ws,            c2r, HW2, y, x0, H2, W2);
        accum_s1p2<16, COB, 4, false>(acc, ws + 16*9*COB, rh,  HW2, y, x0, H2, W2);
    } else {
        accum_s1p2<16, COB, 4, true >(acc, ws,            c2r, HW2, y, x0, H2, W2);
        accum_s1p2<16, COB, 4, true >(acc, ws + 16*9*COB, rh,  HW2, y, x0, H2, W2);
    }
#pragma unroll
    for (int cp = 0; cp < COB/2; cp++) {
        float a00, a10, a01, a11;
        unpack2(acc[cp][0], a00, a10);
        unpack2(acc[cp][1], a01, a11);
        int c0 = co_base + 2*cp, c1 = c0 + 1;
        float2 u0 = *(const float2*)(u + c0 * HW2 + px0);
        float2 u1v = *(const float2*)(u + c1 * HW2 + px0);
        float2 h0 = *(const float2*)(s2old + c0 * HW2 + px0);
        float2 h1 = *(const float2*)(s2old + c1 * HW2 + px0);
        *(float2*)(s2new + c0 * HW2 + px0) = make_float2(
            u0.x * h0.x + (1.f - u0.x) * tanh_fast(a00),
            u0.y * h0.y + (1.f - u0.y) * tanh_fast(a01));
        *(float2*)(s2new + c1 * HW2 + px0) = make_float2(
            u1v.x * h1.x + (1.f - u1v.x) * tanh_fast(a10),
            u1v.y * h1.y + (1.f - u1v.y) * tanh_fast(a11));
    }
}

__device__ __forceinline__ void deconvA_part(
        const float* __restrict__ s2r, const float* __restrict__ w,
        const float* __restrict__ b, const float* __restrict__ s1skip,
        float* __restrict__ up, float* ws, int sub) {
    constexpr int COB = 8;
    load_w_deconv<16, COB, 8>(ws, w, 0);
    __syncthreads();
    int px0 = (sub * 256 + threadIdx.x) * 2;
    int y = px0 / W1, x0 = px0 - y * W1;
    int hx = x0 >> 1;
    u64 acc[4][2];
    init_acc2<COB>(acc, b, 0);
#pragma unroll
    for (int ky = 0; ky < 3; ky++) {
        int t = y + 1 - ky;
        if (t < 0 || (t & 1)) continue;
        int iy = t >> 1;
        if (iy >= H2) continue;
#pragma unroll 4
        for (int ci = 0; ci < 16; ci++) {
            const float* rp = s2r + ci * HW2 + iy * W2;
            float v0 = __ldg(rp + hx);
            float v1 = (hx + 1 < W2) ? __ldg(rp + hx + 1) : 0.0f;
            u64 d0 = pack2(v0, v0), d1 = pack2(v1, v1);
            const u64* w0p = (const u64*)(ws + (ci*9 + ky*3 + 0) * COB);
            const u64* w1p = (const u64*)(ws + (ci*9 + ky*3 + 1) * COB);
            const u64* w2p = (const u64*)(ws + (ci*9 + ky*3 + 2) * COB);
#pragma unroll
            for (int cp = 0; cp < 4; cp++) {
                ffma2(acc[cp][0], w1p[cp], d0);
                ffma2(acc[cp][1], w0p[cp], d1);
                ffma2(acc[cp][1], w2p[cp], d0);
            }
        }
    }
#pragma unroll
    for (int cp = 0; cp < 4; cp++) {
        float e0, e1, o0, o1;
        unpack2(acc[cp][0], e0, e1);
        unpack2(acc[cp][1], o0, o1);
        int c0 = 2*cp, c1 = c0 + 1;
        float2 k0 = *(const float2*)(s1skip + c0 * HW1 + px0);
        float2 k1 = *(const float2*)(s1skip + c1 * HW1 + px0);
        *(float2*)(up + c0 * HW1 + px0) = make_float2(fmaxf(e0 + k0.x, 0.f), fmaxf(o0 + k0.y, 0.f));
        *(float2*)(up + c1 * HW1 + px0) = make_float2(fmaxf(e1 + k1.x, 0.f), fmaxf(o1 + k1.y, 0.f));
    }
}

__device__ __forceinline__ void deconvO_part(
        const float* __restrict__ upr, const float* __restrict__ w,
        const float* __restrict__ b, float* __restrict__ outd,
        float* ws, int sub) {
    for (int i = threadIdx.x; i < 8 * 9; i += 256) ws[i] = w[i];
    __syncthreads();
    int px0 = (sub * 256 + threadIdx.x) * 4;
    int y = px0 / WOUT, x0 = px0 - y * WOUT;
    int hx = x0 >> 1;
    float bias = __ldg(b);
    float acc[4] = {bias, bias, bias, bias};
#pragma unroll
    for (int ky = 0; ky < 3; ky++) {
        int t = y + 1 - ky;
        if (t < 0 || (t & 1)) continue;
        int iy = t >> 1;
        if (iy >= H1) continue;
#pragma unroll
        for (int ci = 0; ci < 8; ci++) {
            const float* rp = upr + ci * HW1 + iy * W1;
            float r0 = __ldg(rp + hx);
            float r1 = (hx + 1 < W1) ? __ldg(rp + hx + 1) : 0.0f;
            float r2 = (hx + 2 < W1) ? __ldg(rp + hx + 2) : 0.0f;
            float w0 = ws[ci*9 + ky*3 + 0];
            float w1 = ws[ci*9 + ky*3 + 1];
            float w2 = ws[ci*9 + ky*3 + 2];
            acc[0] = fmaf(w1, r0, acc[0]);
            acc[1] = fmaf(w0, r1, fmaf(w2, r0, acc[1]));
            acc[2] = fmaf(w1, r1, acc[2]);
            acc[3] = fmaf(w0, r2, fmaf(w2, r1, acc[3]));
        }
    }
    *(float4*)(outd + px0) = make_float4(acc[0], acc[1], acc[2], acc[3]);
}

// ---------------- fused step kernels ----------------------------------------
// K1(i): gates1h tiled [0,640) | conv2(i-1) [640,800) | cand2(i-2) [800,960)
__global__ void __launch_bounds__(256, 4) stepK1(
        const float* c1d, const float* s1r, const float* g1wg, const float* g1bg,
        float* u1, float* rh1,
        const float* c2w, const float* c2bias, float* c2out,
        const float* c2rd, const float* rh2, const float* g2wc, const float* g2bc,
        const float* u2, const float* s2old, float* s2new,
        int en_g1, int en_c2, int en_cd2) {
    __shared__ __align__(16) float ws[1152];
    __shared__ __align__(16) u64 dup[DUPN];
    int bid = blockIdx.x;
    if (bid < 640) {
        if (!en_g1) return;
        gates1h_tile_part(c1d, s1r, g1wg, g1bg, u1, rh1, ws, dup, bid);
    } else if (bid < 800) {
        if (!en_c2) return;
        conv2_part(s1r, c2w, c2bias, c2out, ws, bid - 640);
    } else {
        if (!en_cd2) return;
        cand2_part(c2rd, rh2, g2wc, g2bc, u2, s2old, s2new, ws, bid - 800);
    }
}

// K2(i): cand1h tiled [0,320) | gates2(i-1) [320,640) | deconvA(i-2) [640,800) | deconvO(i-3) [800,1120)
__global__ void __launch_bounds__(256, 4) stepK2(
        const float* c1d, const float* rh1, const float* g1wc, const float* g1bc,
        const float* u1, const float* s1old, float* s1new,
        const float* c2rd, const float* s2rd, const float* g2wg, const float* g2bg,
        float* u2, float* rh2,
        const float* s2dec, const float* u1w, const float* u1bias,
        const float* s1skip, float* upw,
        const float* upr, const float* u2w, const float* u2bias, float* outd,
        int en_c1, int en_g2, int en_dA, int en_dO) {
    __shared__ __align__(16) float ws[1152];
    __shared__ __align__(16) u64 dup[DUPN];
    int bid = blockIdx.x;
    if (bid < 320) {
        if (!en_c1) return;
        cand1h_tile_part(c1d, rh1, g1wc, g1bc, u1, s1old, s1new, ws, dup, bid);
    } else if (bid < 640) {
        if (!en_g2) return;
        gates2_part(c2rd, s2rd, g2wg, g2bg, u2, rh2, ws, bid - 320);
    } else if (bid < 800) {
        if (!en_dA) return;
        deconvA_part(s2dec, u1w, u1bias, s1skip, upw, ws, bid - 640);
    } else {
        if (!en_dO) return;
        deconvO_part(upr, u2w, u2bias, outd, ws, bid - 800);   // 320 blocks = HWO/(256*4)
    }
}

// ---------------- launch ----------------------------------------------------
extern "C" void kernel_launch(void* const* d_in, const int* in_sizes, int n_in,
                              void* d_out, int out_size) {
    const float* vol  = (const float*)d_in[0];
    const float* c1w  = (const float*)d_in[1];
    const float* c1b  = (const float*)d_in[2];
    const float* g1wg = (const float*)d_in[3];
    const float* g1bg = (const float*)d_in[4];
    const float* g1wc = (const float*)d_in[5];
    const float* g1bc = (const float*)d_in[6];
    const float* c2w  = (const float*)d_in[7];
    const float* c2bi = (const float*)d_in[8];
    const float* g2wg = (const float*)d_in[9];
    const float* g2bg = (const float*)d_in[10];
    const float* g2wc = (const float*)d_in[11];
    const float* g2bc = (const float*)d_in[12];
    const float* u1w  = (const float*)d_in[13];
    const float* u1b  = (const float*)d_in[14];
    const float* u2w  = (const float*)d_in[15];
    const float* u2b  = (const float*)d_in[16];
    float* out = (float*)d_out;

    float *s1b0, *s2b0, *c2b0, *upb0, *u1, *rh1, *u2, *rh2, *c1a;
    cudaGetSymbolAddress((void**)&s1b0, g_s1b);
    cudaGetSymbolAddress((void**)&s2b0, g_s2b);
    cudaGetSymbolAddress((void**)&c2b0, g_c2b);
    cudaGetSymbolAddress((void**)&upb0, g_upb);
    cudaGetSymbolAddress((void**)&u1,   g_u1);
    cudaGetSymbolAddress((void**)&rh1,  g_rh1);
    cudaGetSymbolAddress((void**)&u2,   g_u2);
    cudaGetSymbolAddress((void**)&rh2,  g_rh2);
    cudaGetSymbolAddress((void**)&c1a,  g_c1a);

    float* s1b[3] = { s1b0, s1b0 + 8*HW1, s1b0 + 16*HW1 };
    float* s2b[2] = { s2b0, s2b0 + 16*HW2 };
    float* c2b[2] = { c2b0, c2b0 + 16*HW2 };
    float* upb[2] = { upb0, upb0 + 8*HW1 };

    const int TB = 256;
    zero_k<<<(8 * HW1 + TB - 1) / TB, TB>>>(s1b[2], 8 * HW1);
    zero_k<<<(16 * HW2 + TB - 1) / TB, TB>>>(s2b[1], 16 * HW2);

    int nbulk = DEPTH * HW1 / (TB * 2);     // 7680
    conv1_all_k<<<nbulk, TB>>>(vol, c1w, c1b, c1a);

    for (int i = 0; i <= 50; i++) {
        int m3a = ((i - 1) % 3 + 3) % 3;
        int m3w = i % 3;
        int m3d = ((i - 2) % 3 + 3) % 3;
        int c2wi = ((i - 1) % 2 + 2) % 2;
        int c2ri = ((i - 2) % 2 + 2) % 2;
        int s2wi = ((i - 2) % 2 + 2) % 2;
        int s2ri = ((i - 3) % 2 + 2) % 2;
        int upwi = ((i - 2) % 2 + 2) % 2;
        int upri = ((i - 3) % 2 + 2) % 2;

        int gi = (i <= 47) ? i : 47;
        const float* c1d = c1a + (long)gi * 8 * HW1;

        stepK1<<<960, TB>>>(
            c1d, s1b[m3a], g1wg, g1bg, u1, rh1,
            c2w, c2bi, c2b[c2wi],
            c2b[c2ri], rh2, g2wc, g2bc, u2, s2b[s2ri], s2b[s2wi],
            (i <= 47), (i >= 1 && i <= 48), (i >= 2 && i <= 49));

        stepK2<<<1120, TB>>>(
            c1d, rh1, g1wc, g1bc, u1, s1b[m3a], s1b[m3w],
            c2b[c2wi], s2b[s2wi], g2wg, g2bg, u2, rh2,
            s2b[s2wi], u1w, u1b, s1b[m3d], upb[upwi],
            upb[upri], u2w, u2b, out + (long)((i >= 3) ? (i - 3) : 0) * HWO,
            (i <= 47), (i >= 1 && i <= 48), (i >= 2 && i <= 49), (i >= 3));
    }
}

// round 16
// speedup vs baseline: 1.0709x; 1.0709x over previous
#include <cuda_runtime.h>
#include <math.h>

#define H1 256
#define W1 320
#define H2 128
#define W2 160
#define HOUT 512
#define WOUT 640
#define DEPTH 48
#define HW1 (H1*W1)
#define HW2 (H2*W2)
#define HWO (WOUT*HOUT)
#define NB1P2 (HW1/512)   /* 160 */
#define NB2P2 (HW2/512)   /* 40  */

typedef unsigned long long u64;

// ---------------- scratch state ---------------------------------------------
__device__ float g_s1b[3][8  * HW1];
__device__ float g_s2b[2][16 * HW2];
__device__ float g_c2b[2][16 * HW2];
__device__ float g_upb[2][8  * HW1];
__device__ float g_u1 [8  * HW1];
__device__ float g_rh1[8  * HW1];
__device__ float g_u2 [16 * HW2];
__device__ float g_rh2[16 * HW2];
__device__ float g_c1a[DEPTH * 8 * HW1];

// ---------------- packed f32x2 helpers -------------------------------------
__device__ __forceinline__ u64 pack2(float lo, float hi) {
    u64 r; asm("mov.b64 %0, {%1, %2};" : "=l"(r) : "f"(lo), "f"(hi)); return r;
}
__device__ __forceinline__ void unpack2(u64 v, float& lo, float& hi) {
    asm("mov.b64 {%0, %1}, %2;" : "=f"(lo), "=f"(hi) : "l"(v));
}
__device__ __forceinline__ void ffma2(u64& d, u64 a, u64 b) {
    asm("fma.rn.f32x2 %0, %1, %2, %0;" : "+l"(d) : "l"(a), "l"(b));
}
__device__ __forceinline__ float sigf(float x) {
    return __fdividef(1.0f, 1.0f + __expf(-x));
}
__device__ __forceinline__ float tanh_fast(float x) {
    return __fdividef(2.0f, 1.0f + __expf(-2.0f * x)) - 1.0f;
}

// ---------------- weight loaders -------------------------------------------
template<int CIN_TOT, int CSEL, int COB>
__device__ __forceinline__ void load_w_slice(float* ws, const float* __restrict__ w,
                                             int co_base, int ci_off) {
    const int n = CSEL * 9 * COB;
    for (int i = threadIdx.x; i < n; i += blockDim.x) {
        int co   = i % COB;
        int rest = i / COB;
        int ci   = rest / 9;
        int k    = rest - ci * 9;
        ws[i] = w[(co_base + co) * (CIN_TOT * 9) + (ci_off + ci) * 9 + k];
    }
}
template<int CIN, int COB, int COUT_TOT>
__device__ __forceinline__ void load_w_deconv(float* ws, const float* __restrict__ w, int co_base) {
    const int n = CIN * 9 * COB;
    for (int i = threadIdx.x; i < n; i += blockDim.x) {
        int co   = i % COB;
        int rest = i / COB;
        int ci   = rest / 9;
        int k    = rest - ci * 9;
        ws[i] = w[(ci * COUT_TOT + co_base + co) * 9 + k];
    }
}

// ---------------- P2 accumulate cores ----------------------------------------
template<int C, int COB, int CIU, bool GUARD>
__device__ __forceinline__ void accum_s1p2(u64 (&acc)[COB/2][2], const float* ws,
                                           const float* __restrict__ in, int cs,
                                           int y, int x0, int Hin, int Win) {
    const int bx = x0 - 1;
#pragma unroll CIU
    for (int ci = 0; ci < C; ci++) {
        const float* src = in + ci * cs;
        u64 vd[12];
#pragma unroll
        for (int ky = 0; ky < 3; ky++) {
            int iy = y + ky - 1;
            const float* rp = src + iy * Win;
#pragma unroll
            for (int j = 0; j < 4; j++) {
                float v;
                if (GUARD) {
                    int ix = bx + j;
                    v = ((unsigned)iy < (unsigned)Hin && (unsigned)ix < (unsigned)Win)
                        ? __ldg(rp + ix) : 0.0f;
                } else {
                    v = __ldg(rp + bx + j);
                }
                vd[ky * 4 + j] = pack2(v, v);
            }
        }
#pragma unroll
        for (int ky = 0; ky < 3; ky++) {
#pragma unroll
            for (int kx = 0; kx < 3; kx++) {
                const u64* wp = (const u64*)(ws + (ci * 9 + ky * 3 + kx) * COB);
#pragma unroll
                for (int cp = 0; cp < COB / 2; cp++) {
                    u64 w2 = wp[cp];
                    ffma2(acc[cp][0], w2, vd[ky * 4 + kx]);
                    ffma2(acc[cp][1], w2, vd[ky * 4 + kx + 1]);
                }
            }
        }
    }
}
__device__ __forceinline__ bool interior_s1p2(int y, int x0, int Hin, int Win) {
    return (y >= 1) & (y <= Hin - 2) & (x0 >= 1) & (x0 <= Win - 3);
}

template<int C, int COB, int CIU, bool GUARD>
__device__ __forceinline__ void accum_s2p2(u64 (&acc)[COB/2][2], const float* ws,
                                           const float* __restrict__ in, int cs,
                                           int y, int x0, int Hin, int Win) {
    const int bx = 2 * x0 - 1;
#pragma unroll CIU
    for (int ci = 0; ci < C; ci++) {
        const float* src = in + ci * cs;
#pragma unroll
        for (int ky = 0; ky < 3; ky++) {
            int iy = 2 * y + ky - 1;
            const float* rp = src + iy * Win;
            u64 vd[5];
#pragma unroll
            for (int j = 0; j < 5; j++) {
                float v;
                if (GUARD) {
                    int ix = bx + j;
                    v = ((unsigned)iy < (unsigned)Hin && (unsigned)ix < (unsigned)Win)
                        ? __ldg(rp + ix) : 0.0f;
                } else {
                    v = __ldg(rp + bx + j);
                }
                vd[j] = pack2(v, v);
            }
#pragma unroll
            for (int kx = 0; kx < 3; kx++) {
                const u64* wp = (const u64*)(ws + (ci * 9 + ky * 3 + kx) * COB);
#pragma unroll
                for (int cp = 0; cp < COB / 2; cp++) {
                    u64 w2 = wp[cp];
                    ffma2(acc[cp][0], w2, vd[kx]);
                    ffma2(acc[cp][1], w2, vd[kx + 2]);
                }
            }
        }
    }
}
__device__ __forceinline__ bool interior_s2p2(int y, int x0) {
    return (y >= 1) & (x0 >= 1);
}

template<int COB>
__device__ __forceinline__ void init_acc2(u64 (&acc)[COB/2][2], const float* __restrict__ b, int co_base) {
#pragma unroll
    for (int cp = 0; cp < COB/2; cp++) {
        u64 bb = pack2(__ldg(b + co_base + 2*cp), __ldg(b + co_base + 2*cp + 1));
        acc[cp][0] = bb; acc[cp][1] = bb;
    }
}

// ---------------- bulk precompute kernel -------------------------------------
__global__ void zero_k(float* a, int n) {
    int i = blockIdx.x * blockDim.x + threadIdx.x;
    if (i < n) a[i] = 0.0f;
}

__global__ void __launch_bounds__(256, 4) conv1_all_k(
        const float* __restrict__ vol, const float* __restrict__ w,
        const float* __restrict__ b, float* __restrict__ out) {
    constexpr int COB = 8;
    __shared__ __align__(16) float ws[32 * 9 * COB];
    load_w_slice<32, 32, COB>(ws, w, 0, 0);
    __syncthreads();
    int pg = (blockIdx.x * blockDim.x + threadIdx.x) * 2;
    int d  = pg / HW1;
    int px = pg - d * HW1;
    int y = px / W1, x0 = px - y * W1;
    u64 acc[COB/2][2];
    init_acc2<COB>(acc, b, 0);
    const float* in = vol + d * HW1;
    if (interior_s1p2(y, x0, H1, W1))
        accum_s1p2<32, COB, 4, false>(acc, ws, in, DEPTH * HW1, y, x0, H1, W1);
    else
        accum_s1p2<32, COB, 4, true >(acc, ws, in, DEPTH * HW1, y, x0, H1, W1);
    float* op = out + d * 8 * HW1 + px;
#pragma unroll
    for (int cp = 0; cp < COB/2; cp++) {
        float a00, a10, a01, a11;
        unpack2(acc[cp][0], a00, a10);
        unpack2(acc[cp][1], a01, a11);
        *(float2*)(op + (2*cp  ) * HW1) = make_float2(fmaxf(a00,0.f), fmaxf(a01,0.f));
        *(float2*)(op + (2*cp+1) * HW1) = make_float2(fmaxf(a10,0.f), fmaxf(a11,0.f));
    }
}

// ---------------- per-step part bodies (R10 exact) ---------------------------
// gates1h: P2, COB=8, 2 slabs of 160 -> 320 blocks.
__device__ __forceinline__ void gates1h_part(
        const float* __restrict__ c1d, const float* __restrict__ s1r,
        const float* __restrict__ wg, const float* __restrict__ bg,
        float* __restrict__ u_out, float* __restrict__ rh_out,
        float* ws, int sub) {
    constexpr int COB = 8;
    int slab = sub / NB1P2;
    int co_base = slab * COB;
    load_w_slice<16, 16, COB>(ws, wg, co_base, 0);
    __syncthreads();
    int px0 = ((sub - slab * NB1P2) * 256 + threadIdx.x) * 2;
    int y = px0 / W1, x0 = px0 - y * W1;
    u64 acc[COB/2][2];
    init_acc2<COB>(acc, bg, co_base);
    if (interior_s1p2(y, x0, H1, W1)) {
        accum_s1p2<8, COB, 4, false>(acc, ws,           c1d, HW1, y, x0, H1, W1);
        accum_s1p2<8, COB, 4, false>(acc, ws + 8*9*COB, s1r, HW1, y, x0, H1, W1);
    } else {
        accum_s1p2<8, COB, 4, true >(acc, ws,           c1d, HW1, y, x0, H1, W1);
        accum_s1p2<8, COB, 4, true >(acc, ws + 8*9*COB, s1r, HW1, y, x0, H1, W1);
    }
#pragma unroll
    for (int cp = 0; cp < COB/2; cp++) {
        float a00, a10, a01, a11;
        unpack2(acc[cp][0], a00, a10);
        unpack2(acc[cp][1], a01, a11);
        if (slab == 0) {
            int c0 = 2*cp, c1 = c0 + 1;
            float2 h0 = *(const float2*)(s1r + c0 * HW1 + px0);
            float2 h1 = *(const float2*)(s1r + c1 * HW1 + px0);
            *(float2*)(rh_out + c0 * HW1 + px0) = make_float2(sigf(a00)*h0.x, sigf(a01)*h0.y);
            *(float2*)(rh_out + c1 * HW1 + px0) = make_float2(sigf(a10)*h1.x, sigf(a11)*h1.y);
        } else {
            int c0 = 2*cp, c1 = c0 + 1;
            *(float2*)(u_out + c0 * HW1 + px0) = make_float2(sigf(a00), sigf(a01));
            *(float2*)(u_out + c1 * HW1 + px0) = make_float2(sigf(a10), sigf(a11));
        }
    }
}

// cand1h: P2, COB=8, 160 blocks.
__device__ __forceinline__ void cand1h_part(
        const float* __restrict__ c1d, const float* __restrict__ rh,
        const float* __restrict__ wc, const float* __restrict__ bc,
        const float* __restrict__ u, const float* __restrict__ s1old,
        float* __restrict__ s1new, float* ws, int sub) {
    constexpr int COB = 8;
    load_w_slice<16, 16, COB>(ws, wc, 0, 0);
    __syncthreads();
    int px0 = (sub * 256 + threadIdx.x) * 2;
    int y = px0 / W1, x0 = px0 - y * W1;
    u64 acc[COB/2][2];
    init_acc2<COB>(acc, bc, 0);
    if (interior_s1p2(y, x0, H1, W1)) {
        accum_s1p2<8, COB, 4, false>(acc, ws,           c1d, HW1, y, x0, H1, W1);
        accum_s1p2<8, COB, 4, false>(acc, ws + 8*9*COB, rh,  HW1, y, x0, H1, W1);
    } else {
        accum_s1p2<8, COB, 4, true >(acc, ws,           c1d, HW1, y, x0, H1, W1);
        accum_s1p2<8, COB, 4, true >(acc, ws + 8*9*COB, rh,  HW1, y, x0, H1, W1);
    }
#pragma unroll
    for (int cp = 0; cp < COB/2; cp++) {
        float a00, a10, a01, a11;
        unpack2(acc[cp][0], a00, a10);
        unpack2(acc[cp][1], a01, a11);
        int c0 = 2*cp, c1 = c0 + 1;
        float2 u0 = *(const float2*)(u + c0 * HW1 + px0);
        float2 u1v = *(const float2*)(u + c1 * HW1 + px0);
        float2 h0 = *(const float2*)(s1old + c0 * HW1 + px0);
        float2 h1 = *(const float2*)(s1old + c1 * HW1 + px0);
        *(float2*)(s1new + c0 * HW1 + px0) = make_float2(
            u0.x * h0.x + (1.f - u0.x) * tanh_fast(a00),
            u0.y * h0.y + (1.f - u0.y) * tanh_fast(a01));
        *(float2*)(s1new + c1 * HW1 + px0) = make_float2(
            u1v.x * h1.x + (1.f - u1v.x) * tanh_fast(a10),
            u1v.y * h1.y + (1.f - u1v.y) * tanh_fast(a11));
    }
}

// conv2: P2 stride-2, COB=4, 4 slabs of 40 -> 160 blocks.
__device__ __forceinline__ void conv2_part(
        const float* __restrict__ s1r, const float* __restrict__ w,
        const float* __restrict__ b, float* __restrict__ c2out,
        float* ws, int sub) {
    constexpr int COB = 4;
    int slab = sub / NB2P2;
    int co_base = slab * COB;
    load_w_slice<8, 8, COB>(ws, w, co_base, 0);
    __syncthreads();
    int px0 = ((sub - slab * NB2P2) * 256 + threadIdx.x) * 2;
    int y = px0 / W2, x0 = px0 - y * W2;
    u64 acc[COB/2][2];
    init_acc2<COB>(acc, b, co_base);
    if (interior_s2p2(y, x0))
        accum_s2p2<8, COB, 4, false>(acc, ws, s1r, HW1, y, x0, H1, W1);
    else
        accum_s2p2<8, COB, 4, true >(acc, ws, s1r, HW1, y, x0, H1, W1);
#pragma unroll
    for (int cp = 0; cp < COB/2; cp++) {
        float a00, a10, a01, a11;
        unpack2(acc[cp][0], a00, a10);
        unpack2(acc[cp][1], a01, a11);
        int c0 = co_base + 2*cp, c1 = c0 + 1;
        *(float2*)(c2out + c0 * HW2 + px0) = make_float2(fmaxf(a00,0.f), fmaxf(a01,0.f));
        *(float2*)(c2out + c1 * HW2 + px0) = make_float2(fmaxf(a10,0.f), fmaxf(a11,0.f));
    }
}

// gates2: P2, COB=4, 8 slabs of 40 -> 320 blocks.
__device__ __forceinline__ void gates2_part(
        const float* __restrict__ c2r, const float* __restrict__ s2r,
        const float* __restrict__ wg, const float* __restrict__ bg,
        float* __restrict__ u_out, float* __restrict__ rh_out,
        float* ws, int sub) {
    constexpr int COB = 4;
    int slab = sub / NB2P2;
    int co_base = slab * COB;
    load_w_slice<32, 32, COB>(ws, wg, co_base, 0);
    __syncthreads();
    int px0 = ((sub - slab * NB2P2) * 256 + threadIdx.x) * 2;
    int y = px0 / W2, x0 = px0 - y * W2;
    u64 acc[COB/2][2];
    init_acc2<COB>(acc, bg, co_base);
    if (interior_s1p2(y, x0, H2, W2)) {
        accum_s1p2<16, COB, 4, false>(acc, ws,             c2r, HW2, y, x0, H2, W2);
        accum_s1p2<16, COB, 4, false>(acc, ws + 16*9*COB,  s2r, HW2, y, x0, H2, W2);
    } else {
        accum_s1p2<16, COB, 4, true >(acc, ws,             c2r, HW2, y, x0, H2, W2);
        accum_s1p2<16, COB, 4, true >(acc, ws + 16*9*COB,  s2r, HW2, y, x0, H2, W2);
    }
#pragma unroll
    for (int cp = 0; cp < COB/2; cp++) {
        float a00, a10, a01, a11;
        unpack2(acc[cp][0], a00, a10);
        unpack2(acc[cp][1], a01, a11);
        if (co_base < 16) {
            int c0 = co_base + 2*cp, c1 = c0 + 1;
            float2 h0 = *(const float2*)(s2r + c0 * HW2 + px0);
            float2 h1 = *(const float2*)(s2r + c1 * HW2 + px0);
            *(float2*)(rh_out + c0 * HW2 + px0) = make_float2(sigf(a00)*h0.x, sigf(a01)*h0.y);
            *(float2*)(rh_out + c1 * HW2 + px0) = make_float2(sigf(a10)*h1.x, sigf(a11)*h1.y);
        } else {
            int c0 = co_base - 16 + 2*cp, c1 = c0 + 1;
            *(float2*)(u_out + c0 * HW2 + px0) = make_float2(sigf(a00), sigf(a01));
            *(float2*)(u_out + c1 * HW2 + px0) = make_float2(sigf(a10), sigf(a11));
        }
    }
}

// cand2: P2, COB=4, 4 slabs of 40 -> 160 blocks.
__device__ __forceinline__ void cand2_part(
        const float* __restrict__ c2r, const float* __restrict__ rh,
        const float* __restrict__ wc, const float* __restrict__ bc,
        const float* __restrict__ u, const float* __restrict__ s2old,
        float* __restrict__ s2new, float* ws, int sub) {
    constexpr int COB = 4;
    int slab = sub / NB2P2;
    int co_base = slab * COB;
    load_w_slice<32, 32, COB>(ws, wc, co_base, 0);
    __syncthreads();
    int px0 = ((sub - slab * NB2P2) * 256 + threadIdx.x) * 2;
    int y = px0 / W2, x0 = px0 - y * W2;
    u64 acc[COB/2][2];
    init_acc2<COB>(acc, bc, co_base);
    if (interior_s1p2(y, x0, H2, W2)) {
        accum_s1p2<16, COB, 4, false>(acc, ws,            c2r, HW2, y, x0, H2, W2);
        accum_s1p2<16, COB, 4, false>(acc, ws + 16*9*COB, rh,  HW2, y, x0, H2, W2);
    } else {
        accum_s1p2<16, COB, 4, true >(acc, ws,            c2r, HW2, y, x0, H2, W2);
        accum_s1p2<16, COB, 4, true >(acc, ws + 16*9*COB, rh,  HW2, y, x0, H2, W2);
    }
#pragma unroll
    for (int cp = 0; cp < COB/2; cp++) {
        float a00, a10, a01, a11;
        unpack2(acc[cp][0], a00, a10);
        unpack2(acc[cp][1], a01, a11);
        int c0 = co_base + 2*cp, c1 = c0 + 1;
        float2 u0 = *(const float2*)(u + c0 * HW2 + px0);
        float2 u1v = *(const float2*)(u + c1 * HW2 + px0);
        float2 h0 = *(const float2*)(s2old + c0 * HW2 + px0);
        float2 h1 = *(const float2*)(s2old + c1 * HW2 + px0);
        *(float2*)(s2new + c0 * HW2 + px0) = make_float2(
            u0.x * h0.x + (1.f - u0.x) * tanh_fast(a00),
            u0.y * h0.y + (1.f - u0.y) * tanh_fast(a01));
        *(float2*)(s2new + c1 * HW2 + px0) = make_float2(
            u1v.x * h1.x + (1.f - u1v.x) * tanh_fast(a10),
            u1v.y * h1.y + (1.f - u1v.y) * tanh_fast(a11));
    }
}

__device__ __forceinline__ void deconvA_part(
        const float* __restrict__ s2r, const float* __restrict__ w,
        const float* __restrict__ b, const float* __restrict__ s1skip,
        float* __restrict__ up, float* ws, int sub) {
    constexpr int COB = 8;
    load_w_deconv<16, COB, 8>(ws, w, 0);
    __syncthreads();
    int px0 = (sub * 256 + threadIdx.x) * 2;
    int y = px0 / W1, x0 = px0 - y * W1;
    int hx = x0 >> 1;
    u64 acc[4][2];
    init_acc2<COB>(acc, b, 0);
#pragma unroll
    for (int ky = 0; ky < 3; ky++) {
        int t = y + 1 - ky;
        if (t < 0 || (t & 1)) continue;
        int iy = t >> 1;
        if (iy >= H2) continue;
#pragma unroll 4
        for (int ci = 0; ci < 16; ci++) {
            const float* rp = s2r + ci * HW2 + iy * W2;
            float v0 = __ldg(rp + hx);
            float v1 = (hx + 1 < W2) ? __ldg(rp + hx + 1) : 0.0f;
            u64 d0 = pack2(v0, v0), d1 = pack2(v1, v1);
            const u64* w0p = (const u64*)(ws + (ci*9 + ky*3 + 0) * COB);
            const u64* w1p = (const u64*)(ws + (ci*9 + ky*3 + 1) * COB);
            const u64* w2p = (const u64*)(ws + (ci*9 + ky*3 + 2) * COB);
#pragma unroll
            for (int cp = 0; cp < 4; cp++) {
                ffma2(acc[cp][0], w1p[cp], d0);
                ffma2(acc[cp][1], w0p[cp], d1);
                ffma2(acc[cp][1], w2p[cp], d0);
            }
        }
    }
#pragma unroll
    for (int cp = 0; cp < 4; cp++) {
        float e0, e1, o0, o1;
        unpack2(acc[cp][0], e0, e1);
        unpack2(acc[cp][1], o0, o1);
        int c0 = 2*cp, c1 = c0 + 1;
        float2 k0 = *(const float2*)(s1skip + c0 * HW1 + px0);
        float2 k1 = *(const float2*)(s1skip + c1 * HW1 + px0);
        *(float2*)(up + c0 * HW1 + px0) = make_float2(fmaxf(e0 + k0.x, 0.f), fmaxf(o0 + k0.y, 0.f));
        *(float2*)(up + c1 * HW1 + px0) = make_float2(fmaxf(e1 + k1.x, 0.f), fmaxf(o1 + k1.y, 0.f));
    }
}

__device__ __forceinline__ void deconvO_part(
        const float* __restrict__ upr, const float* __restrict__ w,
        const float* __restrict__ b, float* __restrict__ outd,
        float* ws, int sub) {
    for (int i = threadIdx.x; i < 8 * 9; i += 256) ws[i] = w[i];
    __syncthreads();
    int px0 = (sub * 256 + threadIdx.x) * 4;
    int y = px0 / WOUT, x0 = px0 - y * WOUT;
    int hx = x0 >> 1;
    float bias = __ldg(b);
    float acc[4] = {bias, bias, bias, bias};
#pragma unroll
    for (int ky = 0; ky < 3; ky++) {
        int t = y + 1 - ky;
        if (t < 0 || (t & 1)) continue;
        int iy = t >> 1;
        if (iy >= H1) continue;
#pragma unroll
        for (int ci = 0; ci < 8; ci++) {
            const float* rp = upr + ci * HW1 + iy * W1;
            float r0 = __ldg(rp + hx);
            float r1 = (hx + 1 < W1) ? __ldg(rp + hx + 1) : 0.0f;
            float r2 = (hx + 2 < W1) ? __ldg(rp + hx + 2) : 0.0f;
            float w0 = ws[ci*9 + ky*3 + 0];
            float w1 = ws[ci*9 + ky*3 + 1];
            float w2 = ws[ci*9 + ky*3 + 2];
            acc[0] = fmaf(w1, r0, acc[0]);
            acc[1] = fmaf(w0, r1, fmaf(w2, r0, acc[1]));
            acc[2] = fmaf(w1, r1, acc[2]);
            acc[3] = fmaf(w0, r2, fmaf(w2, r1, acc[3]));
        }
    }
    *(float4*)(outd + px0) = make_float4(acc[0], acc[1], acc[2], acc[3]);
}

// ---------------- fused step kernels ----------------------------------------
// K1(i): gates1h(i) [0,320) | conv2(i-1) [320,480) | cand2(i-2) [480,640) | deconvO(i-3) [640,960)
__global__ void __launch_bounds__(256, 4) stepK1(
        const float* c1d, const float* s1r, const float* g1wg, const float* g1bg,
        float* u1, float* rh1,
        const float* c2w, const float* c2bias, float* c2out,
        const float* c2rd, const float* rh2, const float* g2wc, const float* g2bc,
        const float* u2, const float* s2old, float* s2new,
        const float* upr, const float* u2w, const float* u2bias, float* outd,
        int en_g1, int en_c2, int en_cd2, int en_dO) {
    __shared__ __align__(16) float ws[1152];
    int bid = blockIdx.x;
    if (bid < 320) {
        if (!en_g1) return;
        gates1h_part(c1d, s1r, g1wg, g1bg, u1, rh1, ws, bid);
    } else if (bid < 480) {
        if (!en_c2) return;
        conv2_part(s1r, c2w, c2bias, c2out, ws, bid - 320);
    } else if (bid < 640) {
        if (!en_cd2) return;
        cand2_part(c2rd, rh2, g2wc, g2bc, u2, s2old, s2new, ws, bid - 480);
    } else {
        if (!en_dO) return;
        deconvO_part(upr, u2w, u2bias, outd, ws, bid - 640);   // 320 blocks = HWO/(256*4)
    }
}

// K2(i): cand1h(i) [0,160) | gates2(i-1) [160,480) | deconvA(i-2) [480,640)
__global__ void __launch_bounds__(256, 4) stepK2(
        const float* c1d, const float* rh1, const float* g1wc, const float* g1bc,
        const float* u1, const float* s1old, float* s1new,
        const float* c2rd, const float* s2rd, const float* g2wg, const float* g2bg,
        float* u2, float* rh2,
        const float* s2dec, const float* u1w, const float* u1bias,
        const float* s1skip, float* upw,
        int en_c1, int en_g2, int en_dA) {
    __shared__ __align__(16) float ws[1152];
    int bid = blockIdx.x;
    if (bid < 160) {
        if (!en_c1) return;
        cand1h_part(c1d, rh1, g1wc, g1bc, u1, s1old, s1new, ws, bid);
    } else if (bid < 480) {
        if (!en_g2) return;
        gates2_part(c2rd, s2rd, g2wg, g2bg, u2, rh2, ws, bid - 160);
    } else {
        if (!en_dA) return;
        deconvA_part(s2dec, u1w, u1bias, s1skip, upw, ws, bid - 480);
    }
}

// ---------------- launch ----------------------------------------------------
extern "C" void kernel_launch(void* const* d_in, const int* in_sizes, int n_in,
                              void* d_out, int out_size) {
    const float* vol  = (const float*)d_in[0];
    const float* c1w  = (const float*)d_in[1];
    const float* c1b  = (const float*)d_in[2];
    const float* g1wg = (const float*)d_in[3];
    const float* g1bg = (const float*)d_in[4];
    const float* g1wc = (const float*)d_in[5];
    const float* g1bc = (const float*)d_in[6];
    const float* c2w  = (const float*)d_in[7];
    const float* c2bi = (const float*)d_in[8];
    const float* g2wg = (const float*)d_in[9];
    const float* g2bg = (const float*)d_in[10];
    const float* g2wc = (const float*)d_in[11];
    const float* g2bc = (const float*)d_in[12];
    const float* u1w  = (const float*)d_in[13];
    const float* u1b  = (const float*)d_in[14];
    const float* u2w  = (const float*)d_in[15];
    const float* u2b  = (const float*)d_in[16];
    float* out = (float*)d_out;

    float *s1b0, *s2b0, *c2b0, *upb0, *u1, *rh1, *u2, *rh2, *c1a;
    cudaGetSymbolAddress((void**)&s1b0, g_s1b);
    cudaGetSymbolAddress((void**)&s2b0, g_s2b);
    cudaGetSymbolAddress((void**)&c2b0, g_c2b);
    cudaGetSymbolAddress((void**)&upb0, g_upb);
    cudaGetSymbolAddress((void**)&u1,   g_u1);
    cudaGetSymbolAddress((void**)&rh1,  g_rh1);
    cudaGetSymbolAddress((void**)&u2,   g_u2);
    cudaGetSymbolAddress((void**)&rh2,  g_rh2);
    cudaGetSymbolAddress((void**)&c1a,  g_c1a);

    float* s1b[3] = { s1b0, s1b0 + 8*HW1, s1b0 + 16*HW1 };
    float* s2b[2] = { s2b0, s2b0 + 16*HW2 };
    float* c2b[2] = { c2b0, c2b0 + 16*HW2 };
    float* upb[2] = { upb0, upb0 + 8*HW1 };

    const int TB = 256;
    zero_k<<<(8 * HW1 + TB - 1) / TB, TB>>>(s1b[2], 8 * HW1);
    zero_k<<<(16 * HW2 + TB - 1) / TB, TB>>>(s2b[1], 16 * HW2);

    int nbulk = DEPTH * HW1 / (TB * 2);     // 7680
    conv1_all_k<<<nbulk, TB>>>(vol, c1w, c1b, c1a);

    for (int i = 0; i <= 50; i++) {
        int m3a = ((i - 1) % 3 + 3) % 3;
        int m3w = i % 3;
        int m3d = ((i - 2) % 3 + 3) % 3;
        int c2wi = ((i - 1) % 2 + 2) % 2;
        int c2ri = ((i - 2) % 2 + 2) % 2;
        int s2wi = ((i - 2) % 2 + 2) % 2;
        int s2ri = ((i - 3) % 2 + 2) % 2;
        int upwi = ((i - 2) % 2 + 2) % 2;
        int upri = ((i - 3) % 2 + 2) % 2;

        int gi = (i <= 47) ? i : 47;
        const float* c1d = c1a + (long)gi * 8 * HW1;

        // deconvO(i-3) moved into K1: reads upb[upri] written by deconvA in K2(i-1). Safe.
        stepK1<<<960, TB>>>(
            c1d, s1b[m3a], g1wg, g1bg, u1, rh1,
            c2w, c2bi, c2b[c2wi],
            c2b[c2ri], rh2, g2wc, g2bc, u2, s2b[s2ri], s2b[s2wi],
            upb[upri], u2w, u2b, out + (long)((i >= 3) ? (i - 3) : 0) * HWO,
            (i <= 47), (i >= 1 && i <= 48), (i >= 2 && i <= 49), (i >= 3));

        stepK2<<<640, TB>>>(
            c1d, rh1, g1wc, g1bc, u1, s1b[m3a], s1b[m3w],
            c2b[c2wi], s2b[s2wi], g2wg, g2bg, u2, rh2,
            s2b[s2wi], u1w, u1b, s1b[m3d], upb[upwi],
            (i <= 47), (i >= 1 && i <= 48), (i >= 2 && i <= 49));
    }
}